// round 14
// baseline (speedup 1.0000x reference)
#include <cuda_runtime.h>
#include <cuda_bf16.h>

// CumAvgPool1d: y[..., t] = cumsum(x)[..., t] / (t+1)
// x: (8, 512, 16384) fp32 -> 4096 rows of T=16384.
//
// R13: one 512-thread CTA per row (16 warps), 2 CTAs/SM -> only 2 concurrent
// row streams per SM (vs 4 in R11), the next step of the stream-consolidation
// lever that lifted DRAM% in R7/R11, while keeping 32 resident warps/SM.
// Row = 64 chunks of 256 elems; round k = chunks 16k..16k+15, one per warp;
// 4 rounds, 4 barriers/row. Each warp: local scan + 2 interleaved warp
// shuffle scans; publish chunk TOTAL to smem; one __syncthreads; width-16
// shuffle scan combines the round's totals. Depth-2 prefetch ring; all
// loads/stores sector-perfect contiguous 512B; streaming hints.

constexpr int T_LEN  = 16384;
constexpr int T_F4   = T_LEN / 4;          // 4096 float4 per row
constexpr int CHUNK_F4 = 64;               // 256 elems per chunk
constexpr int CHUNKS = T_F4 / CHUNK_F4;    // 64
constexpr int WARPS  = 16;
constexpr int THREADS = WARPS * 32;        // 512
constexpr int ROUNDS = CHUNKS / WARPS;     // 4

__global__ void __launch_bounds__(THREADS, 2)
cumavg_kernel(const float4* __restrict__ x, float4* __restrict__ y)
{
    __shared__ float relay[CHUNKS];

    const int tid  = threadIdx.x;
    const int lane = tid & 31;
    const int warp = tid >> 5;               // 0..15
    const int row  = blockIdx.x;

    const float4* px = x + (size_t)row * T_F4;
    float4*       py = y + (size_t)row * T_F4;

    // depth-2 prefetch ring over this warp's chunks (w, w+16, w+32, w+48)
    float4 ra4[2], rb4[2];
    {
        const int c0 = warp;
        const int c1 = warp + WARPS;
        ra4[0] = __ldcs(px + c0 * CHUNK_F4 + lane);
        rb4[0] = __ldcs(px + c0 * CHUNK_F4 + 32 + lane);
        ra4[1] = __ldcs(px + c1 * CHUNK_F4 + lane);
        rb4[1] = __ldcs(px + c1 * CHUNK_F4 + 32 + lane);
    }

    float carry = 0.0f;
    // divisor base (exact integer floats): chunk c => t0 = c*256 + lane*4
    float tb = (float)(warp * 256 + lane * 4);

    #pragma unroll
    for (int k = 0; k < ROUNDS; ++k) {
        const int c = warp + WARPS * k;

        float4 a = ra4[k & 1];
        float4 b = rb4[k & 1];
        if (k + 2 < ROUNDS) {
            const int cn = c + 2 * WARPS;
            ra4[k & 1] = __ldcs(px + cn * CHUNK_F4 + lane);
            rb4[k & 1] = __ldcs(px + cn * CHUNK_F4 + 32 + lane);
        }

        // two independent local scans (4 elems each)
        float rA = a.x;  a.x = rA;
        rA += a.y;       a.y = rA;
        rA += a.z;       a.z = rA;
        rA += a.w;       a.w = rA;

        float rB = b.x;  b.x = rB;
        rB += b.y;       b.y = rB;
        rB += b.z;       b.z = rB;
        rB += b.w;       b.w = rB;

        // two interleaved warp scans (ILP 2)
        float wA = rA, wB = rB;
        #pragma unroll
        for (int d = 1; d < 32; d <<= 1) {
            float nA = __shfl_up_sync(0xffffffffu, wA, d);
            float nB = __shfl_up_sync(0xffffffffu, wB, d);
            if (lane >= d) { wA += nA; wB += nB; }
        }

        const float totalA = __shfl_sync(0xffffffffu, wA, 31);
        const float totalB = __shfl_sync(0xffffffffu, wB, 31);

        // publish chunk total; HW barrier publishes across warps
        if (lane == 0) relay[c] = totalA + totalB;
        __syncthreads();

        // combine the round's 16 totals: width-16 inclusive shuffle scan
        float s = relay[WARPS * k + (lane & (WARPS - 1))];
        #pragma unroll
        for (int d = 1; d < WARPS; d <<= 1) {
            float n = __shfl_up_sync(0xffffffffu, s, d, WARPS);
            if ((lane & (WARPS - 1)) >= d) s += n;
        }
        const float all = __shfl_sync(0xffffffffu, s, WARPS - 1, WARPS);
        const float pw  = __shfl_sync(0xffffffffu, s, (warp == 0 ? 0 : warp - 1), WARPS);
        const float P   = carry + (warp ? pw : 0.0f);
        carry += all;

        const float offA = P + (wA - rA);            // exclusive prefix, A half
        const float offB = P + totalA + (wB - rB);   // exclusive prefix, B half

        // y[t] = (off + local) / (t+1); divisors via float adds (exact ints)
        float4 o;
        o.x = (offA + a.x) * __fdividef(1.0f, tb + 1.0f);
        o.y = (offA + a.y) * __fdividef(1.0f, tb + 2.0f);
        o.z = (offA + a.z) * __fdividef(1.0f, tb + 3.0f);
        o.w = (offA + a.w) * __fdividef(1.0f, tb + 4.0f);
        __stcs(py + c * CHUNK_F4 + lane, o);

        o.x = (offB + b.x) * __fdividef(1.0f, tb + 129.0f);
        o.y = (offB + b.y) * __fdividef(1.0f, tb + 130.0f);
        o.z = (offB + b.z) * __fdividef(1.0f, tb + 131.0f);
        o.w = (offB + b.w) * __fdividef(1.0f, tb + 132.0f);
        __stcs(py + c * CHUNK_F4 + 32 + lane, o);

        tb += (float)(WARPS * 256);   // next owned chunk is 4096 elems ahead
    }
}

extern "C" void kernel_launch(void* const* d_in, const int* in_sizes, int n_in,
                              void* d_out, int out_size)
{
    const float* x = (const float*)d_in[0];
    float*       y = (float*)d_out;
    const int total = in_sizes[0];
    const int rows  = total / T_LEN;   // 4096 for the reference shape

    cumavg_kernel<<<rows, THREADS>>>((const float4*)x, (float4*)y);
}

// round 15
// speedup vs baseline: 1.0561x; 1.0561x over previous
#include <cuda_runtime.h>
#include <cuda_bf16.h>

// CumAvgPool1d: y[..., t] = cumsum(x)[..., t] / (t+1)
// x: (8, 512, 16384) fp32 -> 4096 rows of T=16384.
//
// R14: R11 base (the empirically optimal config: CTA-per-row, 8 warps,
// 256-elem chunks, depth-2 ring, 4 CTAs/SM, HW-barrier total relay) with
// the round critical path shortened: each warp publishes its chunk TOTAL
// via a fast FADD-tree + 5-step butterfly reduction (~145 cyc after data
// ready) BEFORE running its prefix scans; the scans then overlap the
// barrier wait. All 8 rounds fully unrolled. Loads/stores sector-perfect
// contiguous 512B per instruction; streaming hints (zero reuse).

constexpr int T_LEN  = 16384;
constexpr int T_F4   = T_LEN / 4;          // 4096 float4 per row
constexpr int CHUNK_F4 = 64;               // 256 elems per chunk
constexpr int CHUNKS = T_F4 / CHUNK_F4;    // 64
constexpr int WARPS  = 8;
constexpr int THREADS = WARPS * 32;        // 256
constexpr int ROUNDS = CHUNKS / WARPS;     // 8

__global__ void __launch_bounds__(THREADS)
cumavg_kernel(const float4* __restrict__ x, float4* __restrict__ y)
{
    __shared__ float relay[CHUNKS];

    const int tid  = threadIdx.x;
    const int lane = tid & 31;
    const int warp = tid >> 5;
    const int row  = blockIdx.x;

    const float4* px = x + (size_t)row * T_F4;
    float4*       py = y + (size_t)row * T_F4;

    // depth-2 prefetch ring over this warp's chunks (w, w+8, w+16, ...)
    float4 ra4[2], rb4[2];
    {
        const int c0 = warp;
        const int c1 = warp + WARPS;
        ra4[0] = __ldcs(px + c0 * CHUNK_F4 + lane);
        rb4[0] = __ldcs(px + c0 * CHUNK_F4 + 32 + lane);
        ra4[1] = __ldcs(px + c1 * CHUNK_F4 + lane);
        rb4[1] = __ldcs(px + c1 * CHUNK_F4 + 32 + lane);
    }

    float carry = 0.0f;
    // divisor base (exact integer floats): chunk c => t0 = c*256 + lane*4
    float tb = (float)(warp * 256 + lane * 4);

    #pragma unroll
    for (int k = 0; k < ROUNDS; ++k) {
        const int c = warp + WARPS * k;

        float4 a = ra4[k & 1];
        float4 b = rb4[k & 1];
        if (k + 2 < ROUNDS) {
            const int cn = c + 2 * WARPS;
            ra4[k & 1] = __ldcs(px + cn * CHUNK_F4 + lane);
            rb4[k & 1] = __ldcs(px + cn * CHUNK_F4 + 32 + lane);
        }

        // ---- FAST PATH to publish: lane 8-elem sum (FADD tree) +
        //      butterfly reduction -> chunk total in every lane ----
        float lsum = ((a.x + a.y) + (a.z + a.w)) + ((b.x + b.y) + (b.z + b.w));
        float ct = lsum;
        #pragma unroll
        for (int d = 16; d >= 1; d >>= 1)
            ct += __shfl_xor_sync(0xffffffffu, ct, d);
        if (lane == 0) relay[c] = ct;          // published ~60-80cyc earlier

        // ---- prefix scans (overlap the other warps' publish window) ----
        float rA = a.x;  a.x = rA;
        rA += a.y;       a.y = rA;
        rA += a.z;       a.z = rA;
        rA += a.w;       a.w = rA;

        float rB = b.x;  b.x = rB;
        rB += b.y;       b.y = rB;
        rB += b.z;       b.z = rB;
        rB += b.w;       b.w = rB;

        float wA = rA, wB = rB;
        #pragma unroll
        for (int d = 1; d < 32; d <<= 1) {
            float nA = __shfl_up_sync(0xffffffffu, wA, d);
            float nB = __shfl_up_sync(0xffffffffu, wB, d);
            if (lane >= d) { wA += nA; wB += nB; }
        }
        const float totalA = __shfl_sync(0xffffffffu, wA, 31);

        __syncthreads();

        // combine the round's 8 totals: width-8 inclusive shuffle scan
        float s = relay[WARPS * k + (lane & (WARPS - 1))];
        #pragma unroll
        for (int d = 1; d < WARPS; d <<= 1) {
            float n = __shfl_up_sync(0xffffffffu, s, d, WARPS);
            if ((lane & (WARPS - 1)) >= d) s += n;
        }
        const float all = __shfl_sync(0xffffffffu, s, WARPS - 1, WARPS);
        const float pw  = __shfl_sync(0xffffffffu, s, (warp == 0 ? 0 : warp - 1), WARPS);
        const float P   = carry + (warp ? pw : 0.0f);
        carry += all;

        const float offA = P + (wA - rA);            // exclusive prefix, A half
        const float offB = P + totalA + (wB - rB);   // exclusive prefix, B half

        // y[t] = (off + local) / (t+1); divisors via float adds (exact ints)
        float4 o;
        o.x = (offA + a.x) * __fdividef(1.0f, tb + 1.0f);
        o.y = (offA + a.y) * __fdividef(1.0f, tb + 2.0f);
        o.z = (offA + a.z) * __fdividef(1.0f, tb + 3.0f);
        o.w = (offA + a.w) * __fdividef(1.0f, tb + 4.0f);
        __stcs(py + c * CHUNK_F4 + lane, o);

        o.x = (offB + b.x) * __fdividef(1.0f, tb + 129.0f);
        o.y = (offB + b.y) * __fdividef(1.0f, tb + 130.0f);
        o.z = (offB + b.z) * __fdividef(1.0f, tb + 131.0f);
        o.w = (offB + b.w) * __fdividef(1.0f, tb + 132.0f);
        __stcs(py + c * CHUNK_F4 + 32 + lane, o);

        tb += (float)(WARPS * 256);   // next owned chunk is 2048 elems ahead
    }
}

extern "C" void kernel_launch(void* const* d_in, const int* in_sizes, int n_in,
                              void* d_out, int out_size)
{
    const float* x = (const float*)d_in[0];
    float*       y = (float*)d_out;
    const int total = in_sizes[0];
    const int rows  = total / T_LEN;   // 4096 for the reference shape

    cumavg_kernel<<<rows, THREADS>>>((const float4*)x, (float4*)y);
}